// round 7
// baseline (speedup 1.0000x reference)
#include <cuda_runtime.h>
#include <cstdint>
#include <cstddef>

#define BATCH 8
#define SEQ   1024
#define HID   768
#define ENT   9
#define DIM   64

// ---------------- device scratch (static: no allocation allowed) ----------------
__device__ float g_q[BATCH * ENT * SEQ * DIM];   // [B,E,S,D]  (1/8 scale folded in)
__device__ float g_k[BATCH * ENT * SEQ * DIM];   // [B,E,S,D]
__device__ float g_cos[SEQ * 32];
__device__ float g_sin[SEQ * 32];

typedef unsigned long long ull;

// ---------------- packed f32x2 helpers (Blackwell FFMA2 path) ----------------
__device__ __forceinline__ ull ffma2(ull a, ull b, ull c) {
    ull d;
    asm("fma.rn.f32x2 %0, %1, %2, %3;" : "=l"(d) : "l"(a), "l"(b), "l"(c));
    return d;
}
__device__ __forceinline__ ull dup2(float x) {
    ull r;
    asm("mov.b64 %0, {%1, %1};" : "=l"(r) : "f"(x));
    return r;
}
__device__ __forceinline__ void unpack2(ull v, float& lo, float& hi) {
    asm("mov.b64 {%0, %1}, %2;" : "=f"(lo), "=f"(hi) : "l"(v));
}

// ---------------- RoPE sin/cos table (fp64 for robustness vs fast-math) ----------------
__global__ void rope_table_kernel() {
    int idx = blockIdx.x * blockDim.x + threadIdx.x;
    if (idx >= SEQ * 32) return;
    int pos = idx >> 5;
    int j   = idx & 31;
    double inv = pow(10000.0, -(double)j / 32.0);   // 10000^(-2j/64)
    double ang = (double)pos * inv;
    g_cos[idx] = (float)cos(ang);
    g_sin[idx] = (float)sin(ang);
}

// ---------------- Kernel A: X @ W^T + b, RoPE, scatter to g_q/g_k ----------------
// M = B*S = 8192, N = 1152 (=9*128), K = 768. Tile 128x128, 256 threads, 8x8 microtile.
__global__ void __launch_bounds__(256, 2) proj_rope_kernel(
    const float* __restrict__ X, const float* __restrict__ W,
    const float* __restrict__ bias)
{
    __shared__ float As[16][132];   // [k][m], padded
    __shared__ float Bs[16][132];   // [k][n], padded

    const int tid = threadIdx.x;
    const int tx  = tid & 15;
    const int ty  = tid >> 4;
    const int rowBase = blockIdx.y * 128;
    const int e       = blockIdx.x;          // one ent type per block column
    const int colBase = e * 128;

    ull acc[8][4];
#pragma unroll
    for (int j = 0; j < 8; j++)
#pragma unroll
        for (int q = 0; q < 4; q++) acc[j][q] = 0ULL;

    const int lr = tid >> 2;        // 0..63 (row within half-tile)
    const int lc = (tid & 3) * 4;   // 0,4,8,12 (k offset within 16-chunk)
    const float* Ap = X + (size_t)(rowBase + lr) * HID + lc;
    const float* Bp = W + (size_t)(colBase + lr) * HID + lc;

    // register-staged prefetch of k-chunk 0
    float4 pa0 = *(const float4*)(Ap);
    float4 pa1 = *(const float4*)(Ap + (size_t)64 * HID);
    float4 pb0 = *(const float4*)(Bp);
    float4 pb1 = *(const float4*)(Bp + (size_t)64 * HID);

    for (int kb = 0; kb < HID; kb += 16) {
        // commit staged tile to smem (transposed)
        As[lc+0][lr] = pa0.x; As[lc+1][lr] = pa0.y; As[lc+2][lr] = pa0.z; As[lc+3][lr] = pa0.w;
        As[lc+0][lr+64] = pa1.x; As[lc+1][lr+64] = pa1.y; As[lc+2][lr+64] = pa1.z; As[lc+3][lr+64] = pa1.w;
        Bs[lc+0][lr] = pb0.x; Bs[lc+1][lr] = pb0.y; Bs[lc+2][lr] = pb0.z; Bs[lc+3][lr] = pb0.w;
        Bs[lc+0][lr+64] = pb1.x; Bs[lc+1][lr+64] = pb1.y; Bs[lc+2][lr+64] = pb1.z; Bs[lc+3][lr+64] = pb1.w;
        __syncthreads();

        if (kb + 16 < HID) {                 // prefetch next chunk while computing
            pa0 = *(const float4*)(Ap + kb + 16);
            pa1 = *(const float4*)(Ap + (size_t)64 * HID + kb + 16);
            pb0 = *(const float4*)(Bp + kb + 16);
            pb1 = *(const float4*)(Bp + (size_t)64 * HID + kb + 16);
        }

#pragma unroll
        for (int kk = 0; kk < 16; kk++) {
            float a[8];
            *(float4*)(a)     = *(const float4*)(&As[kk][ty * 8]);
            *(float4*)(a + 4) = *(const float4*)(&As[kk][ty * 8 + 4]);
            ull bp[4];
            *(ulonglong2*)(bp)     = *(const ulonglong2*)(&Bs[kk][tx * 8]);
            *(ulonglong2*)(bp + 2) = *(const ulonglong2*)(&Bs[kk][tx * 8 + 4]);
#pragma unroll
            for (int j = 0; j < 8; j++) {
                ull ad = dup2(a[j]);
#pragma unroll
                for (int q = 0; q < 4; q++)
                    acc[j][q] = ffma2(ad, bp[q], acc[j][q]);
            }
        }
        __syncthreads();
    }

    // ---- epilogue: bias + RoPE (partner via shfl.xor 4) + scatter ----
    float bsr[8];
    *(float4*)(bsr)     = *(const float4*)(bias + colBase + tx * 8);
    *(float4*)(bsr + 4) = *(const float4*)(bias + colBase + tx * 8 + 4);

    const bool is_k   = (tx >= 8);
    const int  dbase  = tx * 8 - (is_k ? 64 : 0);   // dim within [0,64)
    const float scale = is_k ? 1.0f : 0.125f;       // fold 1/sqrt(D) into Q
    float* dst = is_k ? g_k : g_q;

#pragma unroll
    for (int j = 0; j < 8; j++) {
        int m  = rowBase + ty * 8 + j;
        int bi = m >> 10;
        int s  = m & (SEQ - 1);

        float v[8];
#pragma unroll
        for (int q = 0; q < 4; q++) unpack2(acc[j][q], v[2 * q], v[2 * q + 1]);
#pragma unroll
        for (int i = 0; i < 8; i++) v[i] += bsr[i];

        const float* cr = g_cos + s * 32 + (dbase >> 1);
        const float* sr = g_sin + s * 32 + (dbase >> 1);
        float outv[8];
#pragma unroll
        for (int i = 0; i < 8; i++) {
            float partner = __shfl_xor_sync(0xffffffffu, v[i], 4);
            int dd = dbase + i;
            float rot = (dd < 32) ? -partner : partner;   // uniform per thread
            outv[i] = (v[i] * cr[i >> 1] + rot * sr[i >> 1]) * scale;
        }
        float* p = dst + (((size_t)(bi * ENT + e) * SEQ + s) * DIM + dbase);
        *(float4*)(p)     = *(float4*)(outv);
        *(float4*)(p + 4) = *(float4*)(outv + 4);
    }
}

// ---------------- Kernel B: per-(b,e) logits = Q @ K^T with masks ----------------
// 72 batches of [1024,64]x[64,1024]; tile 128x128, 256 threads, 8x8 microtile.
__global__ void __launch_bounds__(256, 2) logits_kernel(
    const float* __restrict__ mask, float* __restrict__ out)
{
    __shared__ float Qs[32][132];
    __shared__ float Ks[32][132];

    const int tid = threadIdx.x;
    const int tx  = tid & 15;
    const int ty  = tid >> 4;
    const int z   = blockIdx.z;           // b*ENT + e
    const int bi  = z / ENT;
    const int nBase = blockIdx.x * 128;
    const int mBase = blockIdx.y * 128;
    const float* Q = g_q + (size_t)z * SEQ * DIM;
    const float* K = g_k + (size_t)z * SEQ * DIM;

    ull acc[8][4];
#pragma unroll
    for (int j = 0; j < 8; j++)
#pragma unroll
        for (int q = 0; q < 4; q++) acc[j][q] = 0ULL;

    const int lr = tid >> 3;        // 0..31
    const int lc = (tid & 7) * 4;   // 0..28

#pragma unroll
    for (int kb = 0; kb < DIM; kb += 32) {
#pragma unroll
        for (int l = 0; l < 4; l++) {
            int r = lr + l * 32;
            float4 v = *(const float4*)(Q + (size_t)(mBase + r) * DIM + kb + lc);
            Qs[lc+0][r] = v.x; Qs[lc+1][r] = v.y; Qs[lc+2][r] = v.z; Qs[lc+3][r] = v.w;
            float4 w = *(const float4*)(K + (size_t)(nBase + r) * DIM + kb + lc);
            Ks[lc+0][r] = w.x; Ks[lc+1][r] = w.y; Ks[lc+2][r] = w.z; Ks[lc+3][r] = w.w;
        }
        __syncthreads();
#pragma unroll
        for (int kk = 0; kk < 32; kk++) {
            float a[8];
            *(float4*)(a)     = *(const float4*)(&Qs[kk][ty * 8]);
            *(float4*)(a + 4) = *(const float4*)(&Qs[kk][ty * 8 + 4]);
            ull bp[4];
            *(ulonglong2*)(bp)     = *(const ulonglong2*)(&Ks[kk][tx * 8]);
            *(ulonglong2*)(bp + 2) = *(const ulonglong2*)(&Ks[kk][tx * 8 + 4]);
#pragma unroll
            for (int j = 0; j < 8; j++) {
                ull ad = dup2(a[j]);
#pragma unroll
                for (int q = 0; q < 4; q++)
                    acc[j][q] = ffma2(ad, bp[q], acc[j][q]);
            }
        }
        __syncthreads();
    }

    float pm[8];
    *(float4*)(pm)     = *(const float4*)(mask + (size_t)bi * SEQ + nBase + tx * 8);
    *(float4*)(pm + 4) = *(const float4*)(mask + (size_t)bi * SEQ + nBase + tx * 8 + 4);

#pragma unroll
    for (int j = 0; j < 8; j++) {
        int mg = mBase + ty * 8 + j;
        float res[8];
#pragma unroll
        for (int q = 0; q < 4; q++) unpack2(acc[j][q], res[2 * q], res[2 * q + 1]);
#pragma unroll
        for (int i = 0; i < 8; i++) {
            int ng = nBase + tx * 8 + i;
            float v = res[i];
            v = v * pm[i] - (1.0f - pm[i]) * 10000.0f;   // padding mask (keys)
            if (mg > ng) v -= 10000.0f;                  // causal (below diagonal)
            res[i] = v;
        }
        float* p = out + ((size_t)z * SEQ + mg) * SEQ + nBase + tx * 8;
        *(float4*)(p)     = *(float4*)(res);
        *(float4*)(p + 4) = *(float4*)(res + 4);
    }
}

// ---------------- launch ----------------
extern "C" void kernel_launch(void* const* d_in, const int* in_sizes, int n_in,
                              void* d_out, int out_size) {
    (void)in_sizes; (void)n_in; (void)out_size;
    const float* X    = (const float*)d_in[0];   // [8,1024,768]
    const float* mask = (const float*)d_in[1];   // [8,1024]
    const float* W    = (const float*)d_in[2];   // [1152,768]
    const float* bias = (const float*)d_in[3];   // [1152]
    float* out = (float*)d_out;                  // [8,9,1024,1024]

    rope_table_kernel<<<(SEQ * 32) / 256, 256>>>();

    dim3 gA(ENT, (BATCH * SEQ) / 128);           // 9 x 64
    proj_rope_kernel<<<gA, 256>>>(X, W, bias);

    dim3 gB(SEQ / 128, SEQ / 128, BATCH * ENT);  // 8 x 8 x 72
    logits_kernel<<<gB, 256>>>(mask, out);
}

// round 10
// speedup vs baseline: 2.2325x; 2.2325x over previous
#include <cuda_runtime.h>
#include <cstdint>
#include <cstddef>

#define BATCH 8
#define SEQ   1024
#define HID   768
#define ENT   9
#define DIM   64

// ---------------- device scratch (static: no allocation allowed) ----------------
// bf16 hi/lo splits, packed u32 (2 bf16 per u32, element 2p in low half)
__device__ __align__(16) uint32_t g_xh[8192 * 384];   // X hi  [8192,768] bf16
__device__ __align__(16) uint32_t g_xl[8192 * 384];   // X lo
__device__ __align__(16) uint32_t g_wh[1152 * 384];   // W hi  [1152,768] bf16
__device__ __align__(16) uint32_t g_wl[1152 * 384];   // W lo
__device__ __align__(16) uint32_t g_qh[BATCH * ENT * SEQ * 32];  // q hi [B*E*S,64] bf16
__device__ __align__(16) uint32_t g_ql[BATCH * ENT * SEQ * 32];
__device__ __align__(16) uint32_t g_kh[BATCH * ENT * SEQ * 32];
__device__ __align__(16) uint32_t g_kl[BATCH * ENT * SEQ * 32];
__device__ float g_cos[SEQ * 32];
__device__ float g_sin[SEQ * 32];

// ---------------- helpers ----------------
__device__ __forceinline__ uint32_t packbf2(float lo, float hi) {
    uint32_t r;
    asm("cvt.rn.satfinite.bf16x2.f32 %0, %1, %2;" : "=r"(r) : "f"(hi), "f"(lo));
    return r;
}
__device__ __forceinline__ float bf_lo_f(uint32_t p) { return __uint_as_float(p << 16); }
__device__ __forceinline__ float bf_hi_f(uint32_t p) { return __uint_as_float(p & 0xFFFF0000u); }

__device__ __forceinline__ uint32_t smem_u32(const void* p) {
    return (uint32_t)__cvta_generic_to_shared(p);
}
__device__ __forceinline__ void cpa16(uint32_t dst, const void* src) {
    asm volatile("cp.async.cg.shared.global [%0], [%1], 16;" :: "r"(dst), "l"(src));
}
__device__ __forceinline__ void cp_commit() {
    asm volatile("cp.async.commit_group;" ::: "memory");
}
__device__ __forceinline__ void cp_wait1() {
    asm volatile("cp.async.wait_group 1;" ::: "memory");
}
__device__ __forceinline__ void cp_wait0() {
    asm volatile("cp.async.wait_group 0;" ::: "memory");
}
__device__ __forceinline__ void ldm4(uint32_t* r, uint32_t addr) {
    asm volatile("ldmatrix.sync.aligned.m8n8.x4.shared.b16 {%0,%1,%2,%3}, [%4];"
                 : "=r"(r[0]), "=r"(r[1]), "=r"(r[2]), "=r"(r[3]) : "r"(addr));
}
__device__ __forceinline__ void mma_bf16(float* c, const uint32_t* a, const uint32_t* b) {
    asm volatile(
        "mma.sync.aligned.m16n8k16.row.col.f32.bf16.bf16.f32 "
        "{%0,%1,%2,%3}, {%4,%5,%6,%7}, {%8,%9}, {%0,%1,%2,%3};"
        : "+f"(c[0]), "+f"(c[1]), "+f"(c[2]), "+f"(c[3])
        : "r"(a[0]), "r"(a[1]), "r"(a[2]), "r"(a[3]), "r"(b[0]), "r"(b[1]));
}

// ---------------- shared GEMM core: compute one 128x128x64 chunk ----------------
// smem tiles: 128 rows x 128 bytes (64 bf16), SW128 swizzle on 16B chunks.
// warp tile 32x64 (wy in 0..3, wx in 0..1); acc[2 mtiles][8 ntiles][4].
__device__ __forceinline__ void mma_chunk(uint32_t aBase, uint32_t bBase,
                                          float acc[2][8][4], int wy, int wx, int lane) {
    const int rsel = (lane & 7) + ((lane >> 3) & 1) * 8;
    const int koff = lane >> 4;   // 0 or 1 (16B k-chunk)
#pragma unroll
    for (int ks = 0; ks < 4; ks++) {
        const int kb = ks * 2 + koff;
        uint32_t a[2][4];
#pragma unroll
        for (int mt = 0; mt < 2; mt++) {
            int r = wy * 32 + mt * 16 + rsel;
            ldm4(a[mt], aBase + (uint32_t)(r * 128 + ((kb ^ (r & 7)) << 4)));
        }
        uint32_t b[8][2];
#pragma unroll
        for (int nt2 = 0; nt2 < 4; nt2++) {
            int r = wx * 64 + nt2 * 16 + rsel;
            uint32_t t[4];
            ldm4(t, bBase + (uint32_t)(r * 128 + ((kb ^ (r & 7)) << 4)));
            b[2 * nt2][0]     = t[0];
            b[2 * nt2 + 1][0] = t[1];
            b[2 * nt2][1]     = t[2];
            b[2 * nt2 + 1][1] = t[3];
        }
#pragma unroll
        for (int mt = 0; mt < 2; mt++)
#pragma unroll
            for (int nt = 0; nt < 8; nt++)
                mma_bf16(acc[mt][nt], a[mt], b[nt]);
    }
}

// ---------------- prep: hi/lo split (+ RoPE table folded into the X pass) ----------------
__global__ void split_kernel(const float* __restrict__ src, int which, int n4) {
    int i = blockIdx.x * blockDim.x + threadIdx.x;
    if (which == 0 && i < SEQ * 32) {
        int pos = i >> 5, j = i & 31;
        double inv = exp2(-(double)j * (13.287712379549449213 / 32.0));  // 10000^(-j/32)
        double ang = (double)pos * inv;
        double t = ang * 0.15915494309189535;   // / (2*pi)
        t -= floor(t);
        float a = (float)(t * 6.283185307179586);
        g_sin[i] = sinf(a);
        g_cos[i] = cosf(a);
    }
    if (i >= n4) return;
    uint32_t* dh = which ? g_wh : g_xh;
    uint32_t* dl = which ? g_wl : g_xl;
    float4 v = ((const float4*)src)[i];
    uint32_t h0 = packbf2(v.x, v.y);
    uint32_t h1 = packbf2(v.z, v.w);
    uint32_t l0 = packbf2(v.x - bf_lo_f(h0), v.y - bf_hi_f(h0));
    uint32_t l1 = packbf2(v.z - bf_lo_f(h1), v.w - bf_hi_f(h1));
    ((uint2*)dh)[i] = make_uint2(h0, h1);
    ((uint2*)dl)[i] = make_uint2(l0, l1);
}

// ---------------- Kernel A: projection GEMM (HMMA) + bias + RoPE epilogue ----------------
// M=8192, N=1152(=9*128), effective K = 768*3 (hi/lo 3-pass as 36 chunks of 64).
// dyn smem: [0..512) bias; buffers @1024: A0,B0,A1,B1 16KB each (total 66560).
__global__ void __launch_bounds__(256, 2) proj_mma_kernel(const float* __restrict__ bias) {
    extern __shared__ __align__(16) uint8_t smem[];
    const uint32_t sbase = smem_u32(smem);
    const int tid = threadIdx.x, wid = tid >> 5, lane = tid & 31;
    const int wy = wid >> 1, wx = wid & 1;
    const int e = blockIdx.x, rowBase = blockIdx.y * 128, colBase = e * 128;

    const uint32_t bufA0 = sbase + 1024;
    const uint32_t bufB0 = sbase + 1024 + 16384;
    const uint32_t bufA1 = sbase + 1024 + 32768;
    const uint32_t bufB1 = sbase + 1024 + 49152;

    if (tid < 128) ((float*)smem)[tid] = bias[colBase + tid];

    float acc[2][8][4];
#pragma unroll
    for (int mt = 0; mt < 2; mt++)
#pragma unroll
        for (int nt = 0; nt < 8; nt++)
#pragma unroll
            for (int q = 0; q < 4; q++) acc[mt][nt][q] = 0.0f;

    const int lr = tid >> 3, lcg = tid & 7;           // load row base, 16B chunk

    // chunk c -> (kblock kc = c/3, pass p = c%3): (Ah,Bh),(Al,Bh),(Ah,Bl)
    auto issue = [&](int c, int b) {
        int kc = c / 3, p = c - kc * 3;
        const uint32_t* As = (p == 1) ? g_xl : g_xh;
        const uint32_t* Bs = (p == 2) ? g_wl : g_wh;
        uint32_t dA = b ? bufA1 : bufA0;
        uint32_t dB = b ? bufB1 : bufB0;
#pragma unroll
        for (int i = 0; i < 4; i++) {
            int r = lr + i * 32, cg = lcg;
            uint32_t so = (uint32_t)(r * 128 + ((cg ^ (r & 7)) << 4));
            cpa16(dA + so, As + (size_t)(rowBase + r) * 384 + kc * 32 + cg * 4);
            cpa16(dB + so, Bs + (size_t)(colBase + r) * 384 + kc * 32 + cg * 4);
        }
        cp_commit();
    };

    issue(0, 0);
    for (int c = 0; c < 36; c++) {
        if (c + 1 < 36) { issue(c + 1, (c + 1) & 1); cp_wait1(); }
        else cp_wait0();
        __syncthreads();
        mma_chunk((c & 1) ? bufA1 : bufA0, (c & 1) ? bufB1 : bufB0, acc, wy, wx, lane);
        __syncthreads();
    }

    // ---- epilogue: bias + RoPE entirely in-lane (pair d <-> d+-32 = ntile t <-> t+4) ----
    const int tig = lane & 3, gq = lane >> 2;
    const float* bias_s = (const float*)smem;
    const float scale = wx ? 1.0f : 0.125f;           // fold 1/sqrt(D) into q
#pragma unroll
    for (int mt = 0; mt < 2; mt++) {
#pragma unroll
        for (int h = 0; h < 2; h++) {
            int m = rowBase + wy * 32 + mt * 16 + h * 8 + gq;
            int bi = m >> 10, s = m & (SEQ - 1);
            const float* cp_ = g_cos + s * 32;
            const float* sp_ = g_sin + s * 32;
            size_t roff = ((size_t)(bi * ENT + e) * SEQ + s) * 32;
            uint32_t* dh = (wx ? g_kh : g_qh) + roff;
            uint32_t* dl = (wx ? g_kl : g_ql) + roff;

            float v[16];
#pragma unroll
            for (int nt = 0; nt < 8; nt++) {
                int f = wx * 64 + nt * 8 + 2 * tig;
                v[2 * nt]     = acc[mt][nt][h * 2]     + bias_s[f];
                v[2 * nt + 1] = acc[mt][nt][h * 2 + 1] + bias_s[f + 1];
            }
#pragma unroll
            for (int nt = 0; nt < 8; nt++) {
                int j = nt * 4 + tig;                 // = (d>>1), shared by the pair
                float cc = cp_[j], ss = sp_[j];
                float p0 = (nt < 4) ? -v[2 * (nt + 4)]     : v[2 * (nt - 4)];
                float p1 = (nt < 4) ? -v[2 * (nt + 4) + 1] : v[2 * (nt - 4) + 1];
                float o0 = (v[2 * nt]     * cc + p0 * ss) * scale;
                float o1 = (v[2 * nt + 1] * cc + p1 * ss) * scale;
                uint32_t hh = packbf2(o0, o1);
                uint32_t ll = packbf2(o0 - bf_lo_f(hh), o1 - bf_hi_f(hh));
                dh[j] = hh;
                dl[j] = ll;
            }
        }
    }
}

// ---------------- Kernel B: logits = Q K^T (HMMA) + masks ----------------
// 72 x [1024 x 1024 x 64]; effective K = 64*3 (hi/lo 3-pass as 3 chunks).
__global__ void __launch_bounds__(256, 2) logits_mma_kernel(
    const float* __restrict__ mask, float* __restrict__ out) {
    extern __shared__ __align__(16) uint8_t smem[];
    const uint32_t sbase = smem_u32(smem);
    const int tid = threadIdx.x, wid = tid >> 5, lane = tid & 31;
    const int wy = wid >> 1, wx = wid & 1;
    const int z = blockIdx.z, bi = z / ENT;
    const int nBase = blockIdx.x * 128;
    const int mBase = blockIdx.y * 128;

    const uint32_t bufA0 = sbase + 1024;
    const uint32_t bufB0 = sbase + 1024 + 16384;
    const uint32_t bufA1 = sbase + 1024 + 32768;
    const uint32_t bufB1 = sbase + 1024 + 49152;

    if (tid < 128) ((float*)smem)[tid] = mask[(size_t)bi * SEQ + nBase + tid];

    float acc[2][8][4];
#pragma unroll
    for (int mt = 0; mt < 2; mt++)
#pragma unroll
        for (int nt = 0; nt < 8; nt++)
#pragma unroll
            for (int q = 0; q < 4; q++) acc[mt][nt][q] = 0.0f;

    const int lr = tid >> 3, lcg = tid & 7;
    const size_t zoff = (size_t)z * SEQ * 32;

    auto issue = [&](int p, int b) {
        const uint32_t* Qs = ((p == 1) ? g_ql : g_qh) + zoff;
        const uint32_t* Ks = ((p == 2) ? g_kl : g_kh) + zoff;
        uint32_t dA = b ? bufA1 : bufA0;
        uint32_t dB = b ? bufB1 : bufB0;
#pragma unroll
        for (int i = 0; i < 4; i++) {
            int r = lr + i * 32, cg = lcg;
            uint32_t so = (uint32_t)(r * 128 + ((cg ^ (r & 7)) << 4));
            cpa16(dA + so, Qs + (size_t)(mBase + r) * 32 + cg * 4);
            cpa16(dB + so, Ks + (size_t)(nBase + r) * 32 + cg * 4);
        }
        cp_commit();
    };

    issue(0, 0);
    for (int c = 0; c < 3; c++) {
        if (c + 1 < 3) { issue(c + 1, (c + 1) & 1); cp_wait1(); }
        else cp_wait0();
        __syncthreads();
        mma_chunk((c & 1) ? bufA1 : bufA0, (c & 1) ? bufB1 : bufB0, acc, wy, wx, lane);
        __syncthreads();
    }

    // ---- epilogue: padding mask + causal mask, fp32 store ----
    const int tig = lane & 3, gq = lane >> 2;
    const float* pm = (const float*)smem;
#pragma unroll
    for (int mt = 0; mt < 2; mt++) {
#pragma unroll
        for (int h = 0; h < 2; h++) {
            int mg = mBase + wy * 32 + mt * 16 + h * 8 + gq;
            float* orow = out + ((size_t)z * SEQ + mg) * SEQ + nBase;
#pragma unroll
            for (int nt = 0; nt < 8; nt++) {
                int col = wx * 64 + nt * 8 + 2 * tig;
                float p0 = pm[col], p1 = pm[col + 1];
                float v0 = acc[mt][nt][h * 2]     * p0 - (1.0f - p0) * 10000.0f;
                float v1 = acc[mt][nt][h * 2 + 1] * p1 - (1.0f - p1) * 10000.0f;
                int ng = nBase + col;
                if (mg > ng)     v0 -= 10000.0f;
                if (mg > ng + 1) v1 -= 10000.0f;
                *(float2*)(orow + col) = make_float2(v0, v1);
            }
        }
    }
}

// ---------------- launch ----------------
extern "C" void kernel_launch(void* const* d_in, const int* in_sizes, int n_in,
                              void* d_out, int out_size) {
    (void)in_sizes; (void)n_in; (void)out_size;
    const float* X    = (const float*)d_in[0];   // [8,1024,768]
    const float* mask = (const float*)d_in[1];   // [8,1024]
    const float* W    = (const float*)d_in[2];   // [1152,768]
    const float* bias = (const float*)d_in[3];   // [1152]
    float* out = (float*)d_out;                  // [8,9,1024,1024]

    const int SMEM = 1024 + 4 * 16384;           // 66560 bytes
    cudaFuncSetAttribute(proj_mma_kernel,   cudaFuncAttributeMaxDynamicSharedMemorySize, SMEM);
    cudaFuncSetAttribute(logits_mma_kernel, cudaFuncAttributeMaxDynamicSharedMemorySize, SMEM);

    const int n4x = 8192 * HID / 4;
    const int n4w = 1152 * HID / 4;
    split_kernel<<<(n4x + 255) / 256, 256>>>(X, 0, n4x);
    split_kernel<<<(n4w + 255) / 256, 256>>>(W, 1, n4w);

    dim3 gA(ENT, (BATCH * SEQ) / 128);           // 9 x 64
    proj_mma_kernel<<<gA, 256, SMEM>>>(bias);

    dim3 gB(SEQ / 128, SEQ / 128, BATCH * ENT);  // 8 x 8 x 72
    logits_mma_kernel<<<gB, 256, SMEM>>>(mask, out);
}

// round 11
// speedup vs baseline: 2.4478x; 1.0965x over previous
#include <cuda_runtime.h>
#include <cstdint>
#include <cstddef>

#define BATCH 8
#define SEQ   1024
#define HID   768
#define ENT   9
#define DIM   64

// ---------------- device scratch (static: no allocation allowed) ----------------
// bf16 hi/lo splits, packed u32 (2 bf16 per u32, element 2p in low half)
__device__ __align__(16) uint32_t g_xh[8192 * 384];   // X hi  [8192,768] bf16
__device__ __align__(16) uint32_t g_xl[8192 * 384];   // X lo
__device__ __align__(16) uint32_t g_wh[1152 * 384];   // W hi  [1152,768] bf16
__device__ __align__(16) uint32_t g_wl[1152 * 384];   // W lo
__device__ __align__(16) uint32_t g_qh[BATCH * ENT * SEQ * 32];  // q hi [B*E*S,64] bf16
__device__ __align__(16) uint32_t g_ql[BATCH * ENT * SEQ * 32];
__device__ __align__(16) uint32_t g_kh[BATCH * ENT * SEQ * 32];
__device__ __align__(16) uint32_t g_kl[BATCH * ENT * SEQ * 32];
__device__ float g_cos[SEQ * 32];
__device__ float g_sin[SEQ * 32];

// ---------------- helpers ----------------
__device__ __forceinline__ uint32_t packbf2(float lo, float hi) {
    uint32_t r;
    asm("cvt.rn.satfinite.bf16x2.f32 %0, %1, %2;" : "=r"(r) : "f"(hi), "f"(lo));
    return r;
}
__device__ __forceinline__ float bf_lo_f(uint32_t p) { return __uint_as_float(p << 16); }
__device__ __forceinline__ float bf_hi_f(uint32_t p) { return __uint_as_float(p & 0xFFFF0000u); }

__device__ __forceinline__ uint32_t smem_u32(const void* p) {
    return (uint32_t)__cvta_generic_to_shared(p);
}
__device__ __forceinline__ void cpa16(uint32_t dst, const void* src) {
    asm volatile("cp.async.cg.shared.global [%0], [%1], 16;" :: "r"(dst), "l"(src));
}
__device__ __forceinline__ void cp_commit() {
    asm volatile("cp.async.commit_group;" ::: "memory");
}
__device__ __forceinline__ void cp_wait1() {
    asm volatile("cp.async.wait_group 1;" ::: "memory");
}
__device__ __forceinline__ void cp_wait0() {
    asm volatile("cp.async.wait_group 0;" ::: "memory");
}
__device__ __forceinline__ void ldm4(uint32_t* r, uint32_t addr) {
    asm volatile("ldmatrix.sync.aligned.m8n8.x4.shared.b16 {%0,%1,%2,%3}, [%4];"
                 : "=r"(r[0]), "=r"(r[1]), "=r"(r[2]), "=r"(r[3]) : "r"(addr));
}
__device__ __forceinline__ void mma_bf16(float* c, const uint32_t* a, const uint32_t* b) {
    asm volatile(
        "mma.sync.aligned.m16n8k16.row.col.f32.bf16.bf16.f32 "
        "{%0,%1,%2,%3}, {%4,%5,%6,%7}, {%8,%9}, {%0,%1,%2,%3};"
        : "+f"(c[0]), "+f"(c[1]), "+f"(c[2]), "+f"(c[3])
        : "r"(a[0]), "r"(a[1]), "r"(a[2]), "r"(a[3]), "r"(b[0]), "r"(b[1]));
}

// ---------------- shared GEMM core: one 128x128x32 k-block, hi|lo packed rows ----------
// smem tile row = 128B: chunks 0-3 = 32 bf16 "hi", chunks 4-7 = 32 bf16 "lo"; SW128 swizzle.
// warp tile 32x64 (wy 0..3, wx 0..1); acc[2 mtiles][8 ntiles][4].
// 3-pass hi/lo product per k16: ah*bh + al*bh + ah*bl (lo*lo dropped).
__device__ __forceinline__ void mma_block(uint32_t aBase, uint32_t bBase,
                                          float acc[2][8][4], int wy, int wx, int lane) {
    const int rsel = (lane & 7) + ((lane >> 3) & 1) * 8;
    const int koff = lane >> 4;   // 0 or 1 (16B chunk within k16)
#pragma unroll
    for (int ks = 0; ks < 2; ks++) {
        const int ch = ks * 2 + koff;   // hi chunk (0..3)
        const int cl = ch + 4;          // lo chunk (4..7)
        uint32_t ah[2][4], al[2][4];
#pragma unroll
        for (int mt = 0; mt < 2; mt++) {
            int r = wy * 32 + mt * 16 + rsel;
            uint32_t rowb = aBase + (uint32_t)(r * 128);
            uint32_t sw = (uint32_t)((r & 7) << 4);
            ldm4(ah[mt], rowb + (((uint32_t)ch << 4) ^ sw));
            ldm4(al[mt], rowb + (((uint32_t)cl << 4) ^ sw));
        }
        uint32_t bh[8][2];
#pragma unroll
        for (int nt2 = 0; nt2 < 4; nt2++) {
            int r = wx * 64 + nt2 * 16 + rsel;
            uint32_t t[4];
            ldm4(t, bBase + (uint32_t)(r * 128 + ((ch ^ (r & 7)) << 4)));
            bh[2 * nt2][0] = t[0]; bh[2 * nt2 + 1][0] = t[1];
            bh[2 * nt2][1] = t[2]; bh[2 * nt2 + 1][1] = t[3];
        }
#pragma unroll
        for (int mt = 0; mt < 2; mt++)
#pragma unroll
            for (int nt = 0; nt < 8; nt++)
                mma_bf16(acc[mt][nt], ah[mt], bh[nt]);
#pragma unroll
        for (int mt = 0; mt < 2; mt++)
#pragma unroll
            for (int nt = 0; nt < 8; nt++)
                mma_bf16(acc[mt][nt], al[mt], bh[nt]);
        uint32_t bl[8][2];
#pragma unroll
        for (int nt2 = 0; nt2 < 4; nt2++) {
            int r = wx * 64 + nt2 * 16 + rsel;
            uint32_t t[4];
            ldm4(t, bBase + (uint32_t)(r * 128 + ((cl ^ (r & 7)) << 4)));
            bl[2 * nt2][0] = t[0]; bl[2 * nt2 + 1][0] = t[1];
            bl[2 * nt2][1] = t[2]; bl[2 * nt2 + 1][1] = t[3];
        }
#pragma unroll
        for (int mt = 0; mt < 2; mt++)
#pragma unroll
            for (int nt = 0; nt < 8; nt++)
                mma_bf16(acc[mt][nt], ah[mt], bl[nt]);
    }
}

// ---------------- prep: hi/lo split (+ RoPE table folded into the X pass) ----------------
__global__ void split_kernel(const float* __restrict__ src, int which, int n4) {
    int i = blockIdx.x * blockDim.x + threadIdx.x;
    if (which == 0 && i < SEQ * 32) {
        int pos = i >> 5, j = i & 31;
        double inv = exp2(-(double)j * (13.287712379549449213 / 32.0));  // 10000^(-j/32)
        double ang = (double)pos * inv;
        double t = ang * 0.15915494309189535;   // / (2*pi)
        t -= floor(t);
        float a = (float)(t * 6.283185307179586);
        g_sin[i] = sinf(a);
        g_cos[i] = cosf(a);
    }
    if (i >= n4) return;
    uint32_t* dh = which ? g_wh : g_xh;
    uint32_t* dl = which ? g_wl : g_xl;
    float4 v = ((const float4*)src)[i];
    uint32_t h0 = packbf2(v.x, v.y);
    uint32_t h1 = packbf2(v.z, v.w);
    uint32_t l0 = packbf2(v.x - bf_lo_f(h0), v.y - bf_hi_f(h0));
    uint32_t l1 = packbf2(v.z - bf_lo_f(h1), v.w - bf_hi_f(h1));
    ((uint2*)dh)[i] = make_uint2(h0, h1);
    ((uint2*)dl)[i] = make_uint2(l0, l1);
}

// ---------------- Kernel A: projection GEMM (HMMA) + bias + RoPE epilogue ----------------
// M=8192, N=1152(=9*128), K=768 as 24 k-blocks of 32 (hi|lo packed rows).
// dyn smem: [0..512) bias; 2 double-buffered 32KB stages @1024 (A 16KB + B 16KB each).
__global__ void __launch_bounds__(256, 2) proj_mma_kernel(const float* __restrict__ bias) {
    extern __shared__ __align__(16) uint8_t smem[];
    const uint32_t sbase = smem_u32(smem);
    const int tid = threadIdx.x, wid = tid >> 5, lane = tid & 31;
    const int wy = wid >> 1, wx = wid & 1;
    const int e = blockIdx.x, rowBase = blockIdx.y * 128, colBase = e * 128;

    if (tid < 128) ((float*)smem)[tid] = bias[colBase + tid];

    float acc[2][8][4];
#pragma unroll
    for (int mt = 0; mt < 2; mt++)
#pragma unroll
        for (int nt = 0; nt < 8; nt++)
#pragma unroll
            for (int q = 0; q < 4; q++) acc[mt][nt][q] = 0.0f;

    const int lr = tid >> 3, lcg = tid & 7;

    auto issue = [&](int kb, int b) {
        uint32_t dA = sbase + 1024 + (uint32_t)b * 32768;
#pragma unroll
        for (int i = 0; i < 4; i++) {
            int r = lr + i * 32, c = lcg;
            uint32_t so = (uint32_t)(r * 128 + ((c ^ (r & 7)) << 4));
            const uint32_t* As = (c < 4) ? g_xh : g_xl;
            const uint32_t* Bs = (c < 4) ? g_wh : g_wl;
            cpa16(dA + so,         As + (size_t)(rowBase + r) * 384 + kb * 16 + (c & 3) * 4);
            cpa16(dA + 16384 + so, Bs + (size_t)(colBase + r) * 384 + kb * 16 + (c & 3) * 4);
        }
        cp_commit();
    };

    issue(0, 0);
    for (int kb = 0; kb < 24; kb++) {
        if (kb + 1 < 24) { issue(kb + 1, (kb + 1) & 1); cp_wait1(); }
        else cp_wait0();
        __syncthreads();
        uint32_t base = sbase + 1024 + (uint32_t)(kb & 1) * 32768;
        mma_block(base, base + 16384, acc, wy, wx, lane);
        __syncthreads();
    }

    // ---- epilogue: bias + RoPE entirely in-lane (pair d <-> d+-32 = ntile t <-> t+4) ----
    const int tig = lane & 3, gq = lane >> 2;
    const float* bias_s = (const float*)smem;
    const float scale = wx ? 1.0f : 0.125f;           // fold 1/sqrt(D) into q
#pragma unroll
    for (int mt = 0; mt < 2; mt++) {
#pragma unroll
        for (int h = 0; h < 2; h++) {
            int m = rowBase + wy * 32 + mt * 16 + h * 8 + gq;
            int bi = m >> 10, s = m & (SEQ - 1);
            const float* cp_ = g_cos + s * 32;
            const float* sp_ = g_sin + s * 32;
            size_t roff = ((size_t)(bi * ENT + e) * SEQ + s) * 32;
            uint32_t* dh = (wx ? g_kh : g_qh) + roff;
            uint32_t* dl = (wx ? g_kl : g_ql) + roff;

            float v[16];
#pragma unroll
            for (int nt = 0; nt < 8; nt++) {
                int f = wx * 64 + nt * 8 + 2 * tig;
                v[2 * nt]     = acc[mt][nt][h * 2]     + bias_s[f];
                v[2 * nt + 1] = acc[mt][nt][h * 2 + 1] + bias_s[f + 1];
            }
#pragma unroll
            for (int nt = 0; nt < 8; nt++) {
                int j = nt * 4 + tig;                 // = (d>>1), shared by the pair
                float cc = cp_[j], ss = sp_[j];
                float p0 = (nt < 4) ? -v[2 * (nt + 4)]     : v[2 * (nt - 4)];
                float p1 = (nt < 4) ? -v[2 * (nt + 4) + 1] : v[2 * (nt - 4) + 1];
                float o0 = (v[2 * nt]     * cc + p0 * ss) * scale;
                float o1 = (v[2 * nt + 1] * cc + p1 * ss) * scale;
                uint32_t hh = packbf2(o0, o1);
                uint32_t ll = packbf2(o0 - bf_lo_f(hh), o1 - bf_hi_f(hh));
                dh[j] = hh;
                dl[j] = ll;
            }
        }
    }
}

// ---------------- Kernel B: logits = Q K^T (HMMA) + masks ----------------
// 72 x [1024 x 1024 x 64]; whole K resident: 2 k-blocks of 32 loaded once, 1 sync.
__global__ void __launch_bounds__(256, 2) logits_mma_kernel(
    const float* __restrict__ mask, float* __restrict__ out) {
    extern __shared__ __align__(16) uint8_t smem[];
    const uint32_t sbase = smem_u32(smem);
    const int tid = threadIdx.x, wid = tid >> 5, lane = tid & 31;
    const int wy = wid >> 1, wx = wid & 1;
    const int z = blockIdx.z, bi = z / ENT;
    const int nBase = blockIdx.x * 128;
    const int mBase = blockIdx.y * 128;

    if (tid < 128) ((float*)smem)[tid] = mask[(size_t)bi * SEQ + nBase + tid];

    const int lr = tid >> 3, lcg = tid & 7;
    const size_t zoff = (size_t)z * SEQ * 32;

    // load both k-blocks (Q hi|lo, K hi|lo) in one shot
#pragma unroll
    for (int kb = 0; kb < 2; kb++) {
        uint32_t dQ = sbase + 1024 + (uint32_t)kb * 32768;
#pragma unroll
        for (int i = 0; i < 4; i++) {
            int r = lr + i * 32, c = lcg;
            uint32_t so = (uint32_t)(r * 128 + ((c ^ (r & 7)) << 4));
            const uint32_t* Qs = ((c < 4) ? g_qh : g_ql) + zoff;
            const uint32_t* Ks = ((c < 4) ? g_kh : g_kl) + zoff;
            cpa16(dQ + so,         Qs + (size_t)(mBase + r) * 32 + kb * 16 + (c & 3) * 4);
            cpa16(dQ + 16384 + so, Ks + (size_t)(nBase + r) * 32 + kb * 16 + (c & 3) * 4);
        }
    }
    cp_commit();

    float acc[2][8][4];
#pragma unroll
    for (int mt = 0; mt < 2; mt++)
#pragma unroll
        for (int nt = 0; nt < 8; nt++)
#pragma unroll
            for (int q = 0; q < 4; q++) acc[mt][nt][q] = 0.0f;

    cp_wait0();
    __syncthreads();
    mma_block(sbase + 1024,         sbase + 1024 + 16384, acc, wy, wx, lane);
    mma_block(sbase + 1024 + 32768, sbase + 1024 + 49152, acc, wy, wx, lane);

    // ---- epilogue: padding mask + causal mask, streaming fp32 store ----
    const int tig = lane & 3, gq = lane >> 2;
    const float* pm = (const float*)smem;
#pragma unroll
    for (int mt = 0; mt < 2; mt++) {
#pragma unroll
        for (int h = 0; h < 2; h++) {
            int mg = mBase + wy * 32 + mt * 16 + h * 8 + gq;
            float* orow = out + ((size_t)z * SEQ + mg) * SEQ + nBase;
#pragma unroll
            for (int nt = 0; nt < 8; nt++) {
                int col = wx * 64 + nt * 8 + 2 * tig;
                float p0 = pm[col], p1 = pm[col + 1];
                float v0 = acc[mt][nt][h * 2]     * p0 - (1.0f - p0) * 10000.0f;
                float v1 = acc[mt][nt][h * 2 + 1] * p1 - (1.0f - p1) * 10000.0f;
                int ng = nBase + col;
                if (mg > ng)     v0 -= 10000.0f;
                if (mg > ng + 1) v1 -= 10000.0f;
                __stcs((float2*)(orow + col), make_float2(v0, v1));
            }
        }
    }
}

// ---------------- launch ----------------
extern "C" void kernel_launch(void* const* d_in, const int* in_sizes, int n_in,
                              void* d_out, int out_size) {
    (void)in_sizes; (void)n_in; (void)out_size;
    const float* X    = (const float*)d_in[0];   // [8,1024,768]
    const float* mask = (const float*)d_in[1];   // [8,1024]
    const float* W    = (const float*)d_in[2];   // [1152,768]
    const float* bias = (const float*)d_in[3];   // [1152]
    float* out = (float*)d_out;                  // [8,9,1024,1024]

    const int SMEM = 1024 + 2 * 32768;           // 66560 bytes
    cudaFuncSetAttribute(proj_mma_kernel,   cudaFuncAttributeMaxDynamicSharedMemorySize, SMEM);
    cudaFuncSetAttribute(logits_mma_kernel, cudaFuncAttributeMaxDynamicSharedMemorySize, SMEM);

    const int n4x = 8192 * HID / 4;
    const int n4w = 1152 * HID / 4;
    split_kernel<<<(n4x + 255) / 256, 256>>>(X, 0, n4x);
    split_kernel<<<(n4w + 255) / 256, 256>>>(W, 1, n4w);

    dim3 gA(ENT, (BATCH * SEQ) / 128);           // 9 x 64
    proj_mma_kernel<<<gA, 256, SMEM>>>(bias);

    dim3 gB(SEQ / 128, SEQ / 128, BATCH * ENT);  // 8 x 8 x 72
    logits_mma_kernel<<<gB, 256, SMEM>>>(mask, out);
}

// round 14
// speedup vs baseline: 2.9583x; 1.2085x over previous
#include <cuda_runtime.h>
#include <cstdint>
#include <cstddef>

#define BATCH 8
#define SEQ   1024
#define HID   768
#define ENT   9
#define DIM   64

// ---------------- device scratch (static: no allocation allowed) ----------------
// bf16 packed u32 (2 bf16 per u32, element 2p in low half)
__device__ __align__(16) uint32_t g_xb[8192 * 384];              // X bf16 [8192,768]
__device__ __align__(16) uint32_t g_wb[1152 * 384];              // W bf16 [1152,768]
__device__ __align__(16) uint32_t g_qb[BATCH * ENT * SEQ * 32];  // q bf16 [B*E*S,64]
__device__ __align__(16) uint32_t g_kb[BATCH * ENT * SEQ * 32];  // k bf16
__device__ float g_cos[SEQ * 32];
__device__ float g_sin[SEQ * 32];

// ---------------- helpers ----------------
__device__ __forceinline__ uint32_t packbf2(float lo, float hi) {
    uint32_t r;
    asm("cvt.rn.satfinite.bf16x2.f32 %0, %1, %2;" : "=r"(r) : "f"(hi), "f"(lo));
    return r;
}
__device__ __forceinline__ uint32_t smem_u32(const void* p) {
    return (uint32_t)__cvta_generic_to_shared(p);
}
__device__ __forceinline__ void cpa16(uint32_t dst, const void* src) {
    asm volatile("cp.async.cg.shared.global [%0], [%1], 16;" :: "r"(dst), "l"(src));
}
__device__ __forceinline__ void cp_commit() {
    asm volatile("cp.async.commit_group;" ::: "memory");
}
__device__ __forceinline__ void cp_wait1() {
    asm volatile("cp.async.wait_group 1;" ::: "memory");
}
__device__ __forceinline__ void cp_wait0() {
    asm volatile("cp.async.wait_group 0;" ::: "memory");
}
__device__ __forceinline__ void ldm4(uint32_t* r, uint32_t addr) {
    asm volatile("ldmatrix.sync.aligned.m8n8.x4.shared.b16 {%0,%1,%2,%3}, [%4];"
                 : "=r"(r[0]), "=r"(r[1]), "=r"(r[2]), "=r"(r[3]) : "r"(addr));
}
__device__ __forceinline__ void mma_bf16(float* c, const uint32_t* a, const uint32_t* b) {
    asm volatile(
        "mma.sync.aligned.m16n8k16.row.col.f32.bf16.bf16.f32 "
        "{%0,%1,%2,%3}, {%4,%5,%6,%7}, {%8,%9}, {%0,%1,%2,%3};"
        : "+f"(c[0]), "+f"(c[1]), "+f"(c[2]), "+f"(c[3])
        : "r"(a[0]), "r"(a[1]), "r"(a[2]), "r"(a[3]), "r"(b[0]), "r"(b[1]));
}

// ---------------- shared GEMM core: one 128x128x64 bf16 k-block ----------------
// smem tile: 128 rows x 128B (64 bf16), SW128 swizzle on 16B chunks.
// warp tile 32x64 (wy 0..3, wx 0..1); acc[2 mtiles][8 ntiles][4].
__device__ __forceinline__ void mma_block64(uint32_t aBase, uint32_t bBase,
                                            float acc[2][8][4], int wy, int wx, int lane) {
    const int rsel = (lane & 7) + ((lane >> 3) & 1) * 8;
    const int koff = lane >> 4;   // 0 or 1 (16B chunk within k16)
#pragma unroll
    for (int ks = 0; ks < 4; ks++) {
        const int kb = ks * 2 + koff;   // chunk 0..7
        uint32_t a[2][4];
#pragma unroll
        for (int mt = 0; mt < 2; mt++) {
            int r = wy * 32 + mt * 16 + rsel;
            ldm4(a[mt], aBase + (uint32_t)(r * 128 + ((kb ^ (r & 7)) << 4)));
        }
        uint32_t b[8][2];
#pragma unroll
        for (int nt2 = 0; nt2 < 4; nt2++) {
            int r = wx * 64 + nt2 * 16 + rsel;
            uint32_t t[4];
            ldm4(t, bBase + (uint32_t)(r * 128 + ((kb ^ (r & 7)) << 4)));
            b[2 * nt2][0] = t[0]; b[2 * nt2 + 1][0] = t[1];
            b[2 * nt2][1] = t[2]; b[2 * nt2 + 1][1] = t[3];
        }
#pragma unroll
        for (int mt = 0; mt < 2; mt++)
#pragma unroll
            for (int nt = 0; nt < 8; nt++)
                mma_bf16(acc[mt][nt], a[mt], b[nt]);
    }
}

// ---------------- prep: bf16 convert (+ RoPE table folded into the X pass) ----------------
__global__ void split_kernel(const float* __restrict__ src, int which, int n4) {
    int i = blockIdx.x * blockDim.x + threadIdx.x;
    if (which == 0 && i < SEQ * 32) {
        int pos = i >> 5, j = i & 31;
        double inv = exp2(-(double)j * (13.287712379549449213 / 32.0));  // 10000^(-j/32)
        double ang = (double)pos * inv;
        double t = ang * 0.15915494309189535;   // / (2*pi)
        t -= floor(t);
        float a = (float)(t * 6.283185307179586);
        g_sin[i] = sinf(a);
        g_cos[i] = cosf(a);
    }
    if (i >= n4) return;
    uint32_t* db = which ? g_wb : g_xb;
    float4 v = ((const float4*)src)[i];
    ((uint2*)db)[i] = make_uint2(packbf2(v.x, v.y), packbf2(v.z, v.w));
}

// ---------------- Kernel A: projection GEMM (bf16 HMMA) + bias + RoPE epilogue ---------
// M=8192, N=1152(=9*128), K=768 as 12 k-blocks of 64; double-buffered smem.
// dyn smem: [0..512) bias; 2 stages @1024 (A 16KB + B 16KB each) = 66560 total.
__global__ void __launch_bounds__(256, 2) proj_mma_kernel(const float* __restrict__ bias) {
    extern __shared__ __align__(16) uint8_t smem[];
    const uint32_t sbase = smem_u32(smem);
    const int tid = threadIdx.x, wid = tid >> 5, lane = tid & 31;
    const int wy = wid >> 1, wx = wid & 1;
    const int e = blockIdx.x, rowBase = blockIdx.y * 128, colBase = e * 128;

    if (tid < 128) ((float*)smem)[tid] = bias[colBase + tid];

    float acc[2][8][4];
#pragma unroll
    for (int mt = 0; mt < 2; mt++)
#pragma unroll
        for (int nt = 0; nt < 8; nt++)
#pragma unroll
            for (int q = 0; q < 4; q++) acc[mt][nt][q] = 0.0f;

    const int lr = tid >> 3, lcg = tid & 7;

    auto issue = [&](int kb, int b) {
        uint32_t dA = sbase + 1024 + (uint32_t)b * 32768;
#pragma unroll
        for (int i = 0; i < 4; i++) {
            int r = lr + i * 32, c = lcg;
            uint32_t so = (uint32_t)(r * 128 + ((c ^ (r & 7)) << 4));
            cpa16(dA + so,         g_xb + (size_t)(rowBase + r) * 384 + kb * 32 + c * 4);
            cpa16(dA + 16384 + so, g_wb + (size_t)(colBase + r) * 384 + kb * 32 + c * 4);
        }
        cp_commit();
    };

    issue(0, 0);
    for (int kb = 0; kb < 12; kb++) {
        if (kb + 1 < 12) { issue(kb + 1, (kb + 1) & 1); cp_wait1(); }
        else cp_wait0();
        __syncthreads();
        uint32_t base = sbase + 1024 + (uint32_t)(kb & 1) * 32768;
        mma_block64(base, base + 16384, acc, wy, wx, lane);
        __syncthreads();
    }

    // ---- epilogue: bias + RoPE entirely in-lane (pair d <-> d+-32 = ntile t <-> t+4) ----
    const int tig = lane & 3, gq = lane >> 2;
    const float* bias_s = (const float*)smem;
    const float scale = wx ? 1.0f : 0.125f;           // fold 1/sqrt(D) into q
#pragma unroll
    for (int mt = 0; mt < 2; mt++) {
#pragma unroll
        for (int h = 0; h < 2; h++) {
            int m = rowBase + wy * 32 + mt * 16 + h * 8 + gq;
            int bi = m >> 10, s = m & (SEQ - 1);
            const float* cp_ = g_cos + s * 32;
            const float* sp_ = g_sin + s * 32;
            size_t roff = ((size_t)(bi * ENT + e) * SEQ + s) * 32;
            uint32_t* db = (wx ? g_kb : g_qb) + roff;

            float v[16];
#pragma unroll
            for (int nt = 0; nt < 8; nt++) {
                int f = wx * 64 + nt * 8 + 2 * tig;
                v[2 * nt]     = acc[mt][nt][h * 2]     + bias_s[f];
                v[2 * nt + 1] = acc[mt][nt][h * 2 + 1] + bias_s[f + 1];
            }
#pragma unroll
            for (int nt = 0; nt < 8; nt++) {
                int j = nt * 4 + tig;                 // = (d>>1), shared by the pair
                float cc = cp_[j], ss = sp_[j];
                float p0 = (nt < 4) ? -v[2 * (nt + 4)]     : v[2 * (nt - 4)];
                float p1 = (nt < 4) ? -v[2 * (nt + 4) + 1] : v[2 * (nt - 4) + 1];
                float o0 = (v[2 * nt]     * cc + p0 * ss) * scale;
                float o1 = (v[2 * nt + 1] * cc + p1 * ss) * scale;
                db[j] = packbf2(o0, o1);
            }
        }
    }
}

// ---------------- Kernel B: logits = Q K^T (bf16 HMMA) + masks ----------------
// 72 x [1024 x 1024 x 64]; whole K=64 resident in one 32KB stage, one sync.
__global__ void __launch_bounds__(256, 2) logits_mma_kernel(
    const float* __restrict__ mask, float* __restrict__ out) {
    extern __shared__ __align__(16) uint8_t smem[];
    const uint32_t sbase = smem_u32(smem);
    const int tid = threadIdx.x, wid = tid >> 5, lane = tid & 31;
    const int wy = wid >> 1, wx = wid & 1;
    const int z = blockIdx.z, bi = z / ENT;
    const int nBase = blockIdx.x * 128;
    const int mBase = blockIdx.y * 128;

    if (tid < 128) ((float*)smem)[tid] = mask[(size_t)bi * SEQ + nBase + tid];

    const int lr = tid >> 3, lcg = tid & 7;
    const size_t zoff = (size_t)z * SEQ * 32;

    {
        uint32_t dQ = sbase + 1024;
#pragma unroll
        for (int i = 0; i < 4; i++) {
            int r = lr + i * 32, c = lcg;
            uint32_t so = (uint32_t)(r * 128 + ((c ^ (r & 7)) << 4));
            cpa16(dQ + so,         g_qb + zoff + (size_t)(mBase + r) * 32 + c * 4);
            cpa16(dQ + 16384 + so, g_kb + zoff + (size_t)(nBase + r) * 32 + c * 4);
        }
        cp_commit();
    }

    float acc[2][8][4];
#pragma unroll
    for (int mt = 0; mt < 2; mt++)
#pragma unroll
        for (int nt = 0; nt < 8; nt++)
#pragma unroll
            for (int q = 0; q < 4; q++) acc[mt][nt][q] = 0.0f;

    cp_wait0();
    __syncthreads();
    mma_block64(sbase + 1024, sbase + 1024 + 16384, acc, wy, wx, lane);

    // ---- epilogue: padding mask + causal mask, streaming fp32 store ----
    const int tig = lane & 3, gq = lane >> 2;
    const float* pm = (const float*)smem;
#pragma unroll
    for (int mt = 0; mt < 2; mt++) {
#pragma unroll
        for (int h = 0; h < 2; h++) {
            int mg = mBase + wy * 32 + mt * 16 + h * 8 + gq;
            float* orow = out + ((size_t)z * SEQ + mg) * SEQ + nBase;
#pragma unroll
            for (int nt = 0; nt < 8; nt++) {
                int col = wx * 64 + nt * 8 + 2 * tig;
                float p0 = pm[col], p1 = pm[col + 1];
                float v0 = acc[mt][nt][h * 2]     * p0 - (1.0f - p0) * 10000.0f;
                float v1 = acc[mt][nt][h * 2 + 1] * p1 - (1.0f - p1) * 10000.0f;
                int ng = nBase + col;
                if (mg > ng)     v0 -= 10000.0f;
                if (mg > ng + 1) v1 -= 10000.0f;
                __stcs((float2*)(orow + col), make_float2(v0, v1));
            }
        }
    }
}

// ---------------- launch ----------------
extern "C" void kernel_launch(void* const* d_in, const int* in_sizes, int n_in,
                              void* d_out, int out_size) {
    (void)in_sizes; (void)n_in; (void)out_size;
    const float* X    = (const float*)d_in[0];   // [8,1024,768]
    const float* mask = (const float*)d_in[1];   // [8,1024]
    const float* W    = (const float*)d_in[2];   // [1152,768]
    const float* bias = (const float*)d_in[3];   // [1152]
    float* out = (float*)d_out;                  // [8,9,1024,1024]

    const int SMEM_P = 1024 + 2 * 32768;         // 66560
    const int SMEM_L = 1024 + 32768;             // 33792
    cudaFuncSetAttribute(proj_mma_kernel,   cudaFuncAttributeMaxDynamicSharedMemorySize, SMEM_P);
    cudaFuncSetAttribute(logits_mma_kernel, cudaFuncAttributeMaxDynamicSharedMemorySize, SMEM_L);

    const int n4x = 8192 * HID / 4;
    const int n4w = 1152 * HID / 4;
    split_kernel<<<(n4x + 255) / 256, 256>>>(X, 0, n4x);
    split_kernel<<<(n4w + 255) / 256, 256>>>(W, 1, n4w);

    dim3 gA(ENT, (BATCH * SEQ) / 128);           // 9 x 64
    proj_mma_kernel<<<gA, 256, SMEM_P>>>(bias);

    dim3 gB(SEQ / 128, SEQ / 128, BATCH * ENT);  // 8 x 8 x 72
    logits_mma_kernel<<<gB, 256, SMEM_L>>>(mask, out);
}

// round 16
// speedup vs baseline: 4.8171x; 1.6283x over previous
#include <cuda_runtime.h>
#include <cstdint>
#include <cstddef>

#define BATCH 8
#define SEQ   1024
#define HID   768
#define ENT   9
#define DIM   64

// ---------------- device scratch (static: no allocation allowed) ----------------
// bf16 packed u32 (2 bf16 per u32, element 2p in low half)
__device__ __align__(16) uint32_t g_xb[8192 * 384];              // X bf16 [8192,768]
__device__ __align__(16) uint32_t g_wb[1152 * 384];              // W bf16 [1152,768]
__device__ __align__(16) uint32_t g_qb[BATCH * ENT * SEQ * 32];  // q bf16 [B*E*S,64]
__device__ __align__(16) uint32_t g_kb[BATCH * ENT * SEQ * 32];  // k bf16
__device__ float g_cos[SEQ * 32];
__device__ float g_sin[SEQ * 32];

// ---------------- helpers ----------------
__device__ __forceinline__ uint32_t packbf2(float lo, float hi) {
    uint32_t r;
    asm("cvt.rn.satfinite.bf16x2.f32 %0, %1, %2;" : "=r"(r) : "f"(hi), "f"(lo));
    return r;
}
__device__ __forceinline__ uint32_t smem_u32(const void* p) {
    return (uint32_t)__cvta_generic_to_shared(p);
}
__device__ __forceinline__ void cpa16(uint32_t dst, const void* src) {
    asm volatile("cp.async.cg.shared.global [%0], [%1], 16;" :: "r"(dst), "l"(src));
}
__device__ __forceinline__ void cp_commit() {
    asm volatile("cp.async.commit_group;" ::: "memory");
}
__device__ __forceinline__ void cp_wait1() {
    asm volatile("cp.async.wait_group 1;" ::: "memory");
}
__device__ __forceinline__ void cp_wait0() {
    asm volatile("cp.async.wait_group 0;" ::: "memory");
}
__device__ __forceinline__ void ldm4(uint32_t* r, uint32_t addr) {
    asm volatile("ldmatrix.sync.aligned.m8n8.x4.shared.b16 {%0,%1,%2,%3}, [%4];"
                 : "=r"(r[0]), "=r"(r[1]), "=r"(r[2]), "=r"(r[3]) : "r"(addr));
}
__device__ __forceinline__ void mma_bf16(float* c, const uint32_t* a, const uint32_t* b) {
    asm volatile(
        "mma.sync.aligned.m16n8k16.row.col.f32.bf16.bf16.f32 "
        "{%0,%1,%2,%3}, {%4,%5,%6,%7}, {%8,%9}, {%0,%1,%2,%3};"
        : "+f"(c[0]), "+f"(c[1]), "+f"(c[2]), "+f"(c[3])
        : "r"(a[0]), "r"(a[1]), "r"(a[2]), "r"(a[3]), "r"(b[0]), "r"(b[1]));
}

// ---------------- shared GEMM core: one 128x128x64 bf16 k-block ----------------
// smem tile: 128 rows x 128B (64 bf16), SW128 swizzle on 16B chunks.
// warp tile 32x64 (wy 0..3, wx 0..1); acc[2 mtiles][8 ntiles][4].
__device__ __forceinline__ void mma_block64(uint32_t aBase, uint32_t bBase,
                                            float acc[2][8][4], int wy, int wx, int lane) {
    const int rsel = (lane & 7) + ((lane >> 3) & 1) * 8;
    const int koff = lane >> 4;   // 0 or 1 (16B chunk within k16)
#pragma unroll
    for (int ks = 0; ks < 4; ks++) {
        const int kb = ks * 2 + koff;   // chunk 0..7
        uint32_t a[2][4];
#pragma unroll
        for (int mt = 0; mt < 2; mt++) {
            int r = wy * 32 + mt * 16 + rsel;
            ldm4(a[mt], aBase + (uint32_t)(r * 128 + ((kb ^ (r & 7)) << 4)));
        }
        uint32_t b[8][2];
#pragma unroll
        for (int nt2 = 0; nt2 < 4; nt2++) {
            int r = wx * 64 + nt2 * 16 + rsel;
            uint32_t t[4];
            ldm4(t, bBase + (uint32_t)(r * 128 + ((kb ^ (r & 7)) << 4)));
            b[2 * nt2][0] = t[0]; b[2 * nt2 + 1][0] = t[1];
            b[2 * nt2][1] = t[2]; b[2 * nt2 + 1][1] = t[3];
        }
#pragma unroll
        for (int mt = 0; mt < 2; mt++)
#pragma unroll
            for (int nt = 0; nt < 8; nt++)
                mma_bf16(acc[mt][nt], a[mt], b[nt]);
    }
}

// ---------------- prep: bf16 convert (+ RoPE table folded into the X pass) ----------------
__global__ void split_kernel(const float* __restrict__ src, int which, int n4) {
    int i = blockIdx.x * blockDim.x + threadIdx.x;
    if (which == 0 && i < SEQ * 32) {
        int pos = i >> 5, j = i & 31;
        double inv = exp2(-(double)j * (13.287712379549449213 / 32.0));  // 10000^(-j/32)
        double ang = (double)pos * inv;
        double t = ang * 0.15915494309189535;   // / (2*pi)
        t -= floor(t);
        float a = (float)(t * 6.283185307179586);
        g_sin[i] = sinf(a);
        g_cos[i] = cosf(a);
    }
    if (i >= n4) return;
    uint32_t* db = which ? g_wb : g_xb;
    float4 v = ((const float4*)src)[i];
    ((uint2*)db)[i] = make_uint2(packbf2(v.x, v.y), packbf2(v.z, v.w));
}

// ---------------- Kernel A: projection GEMM (bf16 HMMA) + bias + RoPE epilogue ---------
// M=8192, N=1152(=9*128), K=768 as 12 k-blocks of 64; double-buffered smem.
// dyn smem: [0..512) bias; 2 stages @1024 (A 16KB + B 16KB each) = 66560 total.
__global__ void __launch_bounds__(256, 2) proj_mma_kernel(const float* __restrict__ bias) {
    extern __shared__ __align__(16) uint8_t smem[];
    const uint32_t sbase = smem_u32(smem);
    const int tid = threadIdx.x, wid = tid >> 5, lane = tid & 31;
    const int wy = wid >> 1, wx = wid & 1;
    const int e = blockIdx.x, rowBase = blockIdx.y * 128, colBase = e * 128;

    if (tid < 128) ((float*)smem)[tid] = bias[colBase + tid];

    float acc[2][8][4];
#pragma unroll
    for (int mt = 0; mt < 2; mt++)
#pragma unroll
        for (int nt = 0; nt < 8; nt++)
#pragma unroll
            for (int q = 0; q < 4; q++) acc[mt][nt][q] = 0.0f;

    const int lr = tid >> 3, lcg = tid & 7;

    auto issue = [&](int kb, int b) {
        uint32_t dA = sbase + 1024 + (uint32_t)b * 32768;
#pragma unroll
        for (int i = 0; i < 4; i++) {
            int r = lr + i * 32, c = lcg;
            uint32_t so = (uint32_t)(r * 128 + ((c ^ (r & 7)) << 4));
            cpa16(dA + so,         g_xb + (size_t)(rowBase + r) * 384 + kb * 32 + c * 4);
            cpa16(dA + 16384 + so, g_wb + (size_t)(colBase + r) * 384 + kb * 32 + c * 4);
        }
        cp_commit();
    };

    issue(0, 0);
    for (int kb = 0; kb < 12; kb++) {
        if (kb + 1 < 12) { issue(kb + 1, (kb + 1) & 1); cp_wait1(); }
        else cp_wait0();
        __syncthreads();
        uint32_t base = sbase + 1024 + (uint32_t)(kb & 1) * 32768;
        mma_block64(base, base + 16384, acc, wy, wx, lane);
        __syncthreads();
    }

    // ---- epilogue: bias + RoPE entirely in-lane (pair d <-> d+-32 = ntile t <-> t+4) ----
    const int tig = lane & 3, gq = lane >> 2;
    const float* bias_s = (const float*)smem;
    const float scale = wx ? 1.0f : 0.125f;           // fold 1/sqrt(D) into q
#pragma unroll
    for (int mt = 0; mt < 2; mt++) {
#pragma unroll
        for (int h = 0; h < 2; h++) {
            int m = rowBase + wy * 32 + mt * 16 + h * 8 + gq;
            int bi = m >> 10, s = m & (SEQ - 1);
            const float* cp_ = g_cos + s * 32;
            const float* sp_ = g_sin + s * 32;
            size_t roff = ((size_t)(bi * ENT + e) * SEQ + s) * 32;
            uint32_t* db = (wx ? g_kb : g_qb) + roff;

            float v[16];
#pragma unroll
            for (int nt = 0; nt < 8; nt++) {
                int f = wx * 64 + nt * 8 + 2 * tig;
                v[2 * nt]     = acc[mt][nt][h * 2]     + bias_s[f];
                v[2 * nt + 1] = acc[mt][nt][h * 2 + 1] + bias_s[f + 1];
            }
#pragma unroll
            for (int nt = 0; nt < 8; nt++) {
                int j = nt * 4 + tig;                 // = (d>>1), shared by the pair
                float cc = cp_[j], ss = sp_[j];
                float p0 = (nt < 4) ? -v[2 * (nt + 4)]     : v[2 * (nt - 4)];
                float p1 = (nt < 4) ? -v[2 * (nt + 4) + 1] : v[2 * (nt - 4) + 1];
                float o0 = (v[2 * nt]     * cc + p0 * ss) * scale;
                float o1 = (v[2 * nt + 1] * cc + p1 * ss) * scale;
                db[j] = packbf2(o0, o1);
            }
        }
    }
}

// ---------------- Kernel B: logits = Q K^T (bf16 HMMA), K-strip pipelined ----------------
// One CTA per (m-tile, z): 128 rows x full 1024 cols. Q resident; K tiles double-buffered;
// stores of tile kt overlap loads of tile kt+2 and MMA of kt+1.
// dyn smem: mask [0,4096); Q @4096 (16KB); K0 @20480; K1 @36864  => 53248 B.
__global__ void __launch_bounds__(256, 2) logits_mma_kernel(
    const float* __restrict__ mask, float* __restrict__ out) {
    extern __shared__ __align__(16) uint8_t smem[];
    const uint32_t sbase = smem_u32(smem);
    const int tid = threadIdx.x, wid = tid >> 5, lane = tid & 31;
    const int wy = wid >> 1, wx = wid & 1;
    const int z = blockIdx.y, bi = z / ENT;
    const int mBase = blockIdx.x * 128;
    const size_t zoff = (size_t)z * SEQ * 32;

    // full mask row (1024 floats)
#pragma unroll
    for (int i = 0; i < 4; i++)
        ((float*)smem)[tid + i * 256] = mask[(size_t)bi * SEQ + tid + i * 256];

    const int lr = tid >> 3, lcg = tid & 7;
    const uint32_t qBase = sbase + 4096;
    const uint32_t kBase0 = sbase + 20480;

    // Q tile (group 0)
#pragma unroll
    for (int i = 0; i < 4; i++) {
        int r = lr + i * 32, c = lcg;
        uint32_t so = (uint32_t)(r * 128 + ((c ^ (r & 7)) << 4));
        cpa16(qBase + so, g_qb + zoff + (size_t)(mBase + r) * 32 + c * 4);
    }
    cp_commit();

    auto issueK = [&](int kt, int b) {
        uint32_t dK = kBase0 + (uint32_t)b * 16384;
#pragma unroll
        for (int i = 0; i < 4; i++) {
            int r = lr + i * 32, c = lcg;
            uint32_t so = (uint32_t)(r * 128 + ((c ^ (r & 7)) << 4));
            cpa16(dK + so, g_kb + zoff + (size_t)(kt * 128 + r) * 32 + c * 4);
        }
        cp_commit();
    };

    issueK(0, 0);
    issueK(1, 1);

    const int tig = lane & 3, gq = lane >> 2;
    const float* pm = (const float*)smem;

    for (int kt = 0; kt < 8; kt++) {
        if (kt < 7) cp_wait1(); else cp_wait0();   // K tile kt (and Q) complete
        __syncthreads();

        float acc[2][8][4];
#pragma unroll
        for (int mt = 0; mt < 2; mt++)
#pragma unroll
            for (int nt = 0; nt < 8; nt++)
#pragma unroll
                for (int q = 0; q < 4; q++) acc[mt][nt][q] = 0.0f;

        mma_block64(qBase, kBase0 + (uint32_t)(kt & 1) * 16384, acc, wy, wx, lane);

        // ---- epilogue for this K tile: padding + causal masks, streaming stores ----
#pragma unroll
        for (int mt = 0; mt < 2; mt++) {
#pragma unroll
            for (int h = 0; h < 2; h++) {
                int mg = mBase + wy * 32 + mt * 16 + h * 8 + gq;
                float* orow = out + ((size_t)z * SEQ + mg) * SEQ + kt * 128;
#pragma unroll
                for (int nt = 0; nt < 8; nt++) {
                    int col = wx * 64 + nt * 8 + 2 * tig;
                    int gcol = kt * 128 + col;
                    float p0 = pm[gcol], p1 = pm[gcol + 1];
                    float v0 = acc[mt][nt][h * 2]     * p0 - (1.0f - p0) * 10000.0f;
                    float v1 = acc[mt][nt][h * 2 + 1] * p1 - (1.0f - p1) * 10000.0f;
                    if (mg > gcol)     v0 -= 10000.0f;
                    if (mg > gcol + 1) v1 -= 10000.0f;
                    __stcs((float2*)(orow + col), make_float2(v0, v1));
                }
            }
        }
        __syncthreads();
        if (kt + 2 < 8) issueK(kt + 2, kt & 1);
    }
}

// ---------------- launch ----------------
extern "C" void kernel_launch(void* const* d_in, const int* in_sizes, int n_in,
                              void* d_out, int out_size) {
    (void)in_sizes; (void)n_in; (void)out_size;
    const float* X    = (const float*)d_in[0];   // [8,1024,768]
    const float* mask = (const float*)d_in[1];   // [8,1024]
    const float* W    = (const float*)d_in[2];   // [1152,768]
    const float* bias = (const float*)d_in[3];   // [1152]
    float* out = (float*)d_out;                  // [8,9,1024,1024]

    const int SMEM_P = 1024 + 2 * 32768;         // 66560
    const int SMEM_L = 4096 + 3 * 16384;         // 53248
    cudaFuncSetAttribute(proj_mma_kernel,   cudaFuncAttributeMaxDynamicSharedMemorySize, SMEM_P);
    cudaFuncSetAttribute(logits_mma_kernel, cudaFuncAttributeMaxDynamicSharedMemorySize, SMEM_L);

    const int n4x = 8192 * HID / 4;
    const int n4w = 1152 * HID / 4;
    split_kernel<<<(n4x + 255) / 256, 256>>>(X, 0, n4x);
    split_kernel<<<(n4w + 255) / 256, 256>>>(W, 1, n4w);

    dim3 gA(ENT, (BATCH * SEQ) / 128);           // 9 x 64
    proj_mma_kernel<<<gA, 256, SMEM_P>>>(bias);

    dim3 gB(SEQ / 128, BATCH * ENT);             // 8 m-tiles x 72 z
    logits_mma_kernel<<<gB, 256, SMEM_L>>>(mask, out);
}